// round 12
// baseline (speedup 1.0000x reference)
#include <cuda_runtime.h>
#include <cuda_fp16.h>
#include <math.h>
#include <stdint.h>

// ---------------------------------------------------------------------------
// B=2, S=2048, D=2048, H=16, HD=128.
// attn[i] = ( sum_{j<i} v_j + exp(s_ii)*v_i ) / (i + sum_{j>=i} exp(s_ij))
// fp16 mma.sync m16n8k16 (fp32 accum), ldmatrix, SW128, 3-stage cp.async.
// R11 base (525us) + single-barrier multistage mainloop (bisected alone).
// ---------------------------------------------------------------------------

namespace {
constexpr int B_  = 2;
constexpr int S_  = 2048;
constexpr int D_  = 2048;
constexpr int H_  = 16;
constexpr int HD_ = 128;
constexpr int BH_ = B_ * H_;     // 32
constexpr int M_  = B_ * S_;     // 4096
constexpr int NC_ = 32;
constexpr int CH_ = S_ / NC_;    // 64

constexpr int KB    = 64;                  // K halfs per block (128B rows)
constexpr int TILEB = 128 * 128;           // 16KB per 128x64h tile
constexpr int NST   = 3;
constexpr unsigned DS_GEMM = NST * 2 * TILEB;         // 98304
constexpr unsigned DS_QK   = 2 * TILEB + NST * TILEB; // 81920
constexpr float SCALE = 0.02209708691207961f;  // 1/sqrt(2048)

constexpr long NX8 = (long)M_ * D_ / 8;   // 1048576 (2 regions of NW8)
constexpr long NW8 = (long)D_ * D_ / 8;   // 524288 = 2^19
}

// Scratch (static device arrays).
__device__ __half g_xh [(size_t)M_ * D_];
__device__ __half g_wqh[(size_t)D_ * D_];
__device__ __half g_wkh[(size_t)D_ * D_];
__device__ __half g_wvh[(size_t)D_ * D_];
__device__ __half g_woh[(size_t)D_ * D_];
__device__ __half g_qh [(size_t)M_ * D_];
__device__ __half g_kh [(size_t)M_ * D_];
__device__ __half g_cch[(size_t)M_ * D_];
__device__ float  g_v  [(size_t)M_ * D_];
__device__ float  g_dinv [BH_ * S_];
__device__ float  g_ediag[BH_ * S_];
__device__ float  g_csum [BH_ * NC_ * HD_];

// ---------------------------------------------------------------------------
__device__ __forceinline__ uint32_t h2u(__half2 h) {
  return *reinterpret_cast<uint32_t*>(&h);
}

__device__ __forceinline__ void cp16s(uint32_t dst, const void* src) {
  asm volatile("cp.async.cg.shared.global [%0], [%1], 16;" :: "r"(dst), "l"(src));
}
__device__ __forceinline__ void cp_commit() { asm volatile("cp.async.commit_group;"); }
template <int N> __device__ __forceinline__ void cp_wait() {
  asm volatile("cp.async.wait_group %0;" :: "n"(N));
}

__device__ __forceinline__ void mma16(float c[4], const uint32_t a[4],
                                      uint32_t b0, uint32_t b1) {
  asm volatile(
      "mma.sync.aligned.m16n8k16.row.col.f32.f16.f16.f32 "
      "{%0,%1,%2,%3},{%4,%5,%6,%7},{%8,%9},{%0,%1,%2,%3};"
      : "+f"(c[0]), "+f"(c[1]), "+f"(c[2]), "+f"(c[3])
      : "r"(a[0]), "r"(a[1]), "r"(a[2]), "r"(a[3]), "r"(b0), "r"(b1));
}

__device__ __forceinline__ void ldm4(uint32_t r[4], uint32_t addr) {
  asm volatile("ldmatrix.sync.aligned.m8n8.x4.shared.b16 {%0,%1,%2,%3}, [%4];"
               : "=r"(r[0]), "=r"(r[1]), "=r"(r[2]), "=r"(r[3]) : "r"(addr));
}

#define SWZ(x) ((x) ^ (((x) >> 3) & 0x70))

// Load a 128-row x 64-half tile (row stride ldK halfs) into swizzled smem.
__device__ __forceinline__ void ld_tile(uint32_t sbase, const __half* g,
                                        long ldK, int tid) {
#pragma unroll
  for (int i = 0; i < 4; ++i) {
    const int id  = tid + i * 256;     // 0..1023
    const int row = id >> 3;           // 0..127
    const int cb  = (id & 7) << 4;     // byte col
    const int off = row * 128 + cb;
    cp16s(sbase + SWZ(off), g + (long)row * ldK + (cb >> 1));
  }
}

// One 64-half K block: 4 k16 steps; warp tile 32x64.
__device__ __forceinline__ void mma_block(uint32_t aBase, uint32_t bBase,
                                          int warpM, int warpN, int lane,
                                          float acc[2][8][4]) {
  const int mi = lane >> 3;
  const int rA = (lane & 7) + ((mi & 1) << 3);
  const int cA = (mi >> 1) << 4;
  const int rB = (lane & 7) + ((mi >> 1) << 3);
  const int cB = (mi & 1) << 4;
#pragma unroll
  for (int ks = 0; ks < 4; ++ks) {
    const int kb = ks * 32;
    uint32_t a[2][4];
#pragma unroll
    for (int m = 0; m < 2; ++m) {
      const int off = (warpM * 32 + m * 16 + rA) * 128 + kb + cA;
      ldm4(a[m], aBase + SWZ(off));
    }
#pragma unroll
    for (int p = 0; p < 4; ++p) {
      uint32_t b[4];
      const int off = (warpN * 64 + p * 16 + rB) * 128 + kb + cB;
      ldm4(b, bBase + SWZ(off));
      mma16(acc[0][2 * p],     a[0], b[0], b[1]);
      mma16(acc[1][2 * p],     a[1], b[0], b[1]);
      mma16(acc[0][2 * p + 1], a[0], b[2], b[3]);
      mma16(acc[1][2 * p + 1], a[1], b[2], b[3]);
    }
  }
}

// ---------------------------------------------------------------------------
// C[M,N] = A[M,K](h) * Bw[N,K](h)^T + bias. Output fp16 (Ch) or fp32 (Cf).
// Single-barrier multistage: wait -> sync -> prefetch -> compute.
// ---------------------------------------------------------------------------
__global__ __launch_bounds__(256)
void gemm_h(const __half* __restrict__ A, const __half* __restrict__ Bw,
            const float* __restrict__ bias, __half* __restrict__ Ch,
            float* __restrict__ Cf, int K) {
  extern __shared__ __align__(128) uint8_t dyn[];
  const uint32_t sb = (uint32_t)__cvta_generic_to_shared(dyn);
  const int tid = threadIdx.x, lane = tid & 31, warp = tid >> 5;
  const int warpM = warp & 3, warpN = warp >> 2;
  const long mBase = (long)blockIdx.y * 128;
  const long nBase = (long)blockIdx.x * 128;
  const __half* Ab = A + mBase * (long)K;
  const __half* Bb = Bw + nBase * (long)K;

  float acc[2][8][4];
#pragma unroll
  for (int m = 0; m < 2; ++m)
#pragma unroll
    for (int n = 0; n < 8; ++n)
#pragma unroll
      for (int c = 0; c < 4; ++c) acc[m][n][c] = 0.0f;

  const int NIT = K / KB;  // 32
#pragma unroll
  for (int s = 0; s < NST - 1; ++s) {
    ld_tile(sb + s * 2 * TILEB,         Ab + s * KB, K, tid);
    ld_tile(sb + s * 2 * TILEB + TILEB, Bb + s * KB, K, tid);
    cp_commit();
  }

  for (int it = 0; it < NIT; ++it) {
    cp_wait<NST - 2>();
    __syncthreads();
    const int nx = it + NST - 1;
    if (nx < NIT) {
      const int ns = nx % NST;
      ld_tile(sb + ns * 2 * TILEB,         Ab + (long)nx * KB, K, tid);
      ld_tile(sb + ns * 2 * TILEB + TILEB, Bb + (long)nx * KB, K, tid);
    }
    cp_commit();
    const int slot = it % NST;
    mma_block(sb + slot * 2 * TILEB, sb + slot * 2 * TILEB + TILEB,
              warpM, warpN, lane, acc);
  }

#pragma unroll
  for (int m = 0; m < 2; ++m) {
    const long r0 = mBase + warpM * 32 + m * 16 + (lane >> 2);
#pragma unroll
    for (int n = 0; n < 8; ++n) {
      const long col = nBase + warpN * 64 + n * 8 + (lane & 3) * 2;
      const float b0 = bias[col], b1 = bias[col + 1];
      const float v0 = acc[m][n][0] + b0, v1 = acc[m][n][1] + b1;
      const float v2 = acc[m][n][2] + b0, v3 = acc[m][n][3] + b1;
      if (Ch) {
        *(uint32_t*)(Ch + r0 * (long)D_ + col)       = h2u(__floats2half2_rn(v0, v1));
        *(uint32_t*)(Ch + (r0 + 8) * (long)D_ + col) = h2u(__floats2half2_rn(v2, v3));
      } else {
        *(float2*)(Cf + r0 * (long)D_ + col)       = make_float2(v0, v1);
        *(float2*)(Cf + (r0 + 8) * (long)D_ + col) = make_float2(v2, v3);
      }
    }
  }
}

// ---------------------------------------------------------------------------
// QK^T upper-triangle exp row sums. Q cached; K tiles streamed; single barrier.
// ---------------------------------------------------------------------------
__global__ __launch_bounds__(256)
void qk_rowsum_h(const __half* __restrict__ Q, const __half* __restrict__ Km,
                 float* __restrict__ dinv, float* __restrict__ ediag) {
  extern __shared__ __align__(128) uint8_t dyn[];
  __shared__ float rsS[128];
  const uint32_t sQ    = (uint32_t)__cvta_generic_to_shared(dyn);
  const uint32_t sRing = sQ + 2 * TILEB;
  const int tid = threadIdx.x, lane = tid & 31, warp = tid >> 5;
  const int warpM = warp & 3, warpN = warp >> 2;
  const int itile = blockIdx.x, bh = blockIdx.y;
  const int b = bh >> 4, h = bh & 15;
  const __half* qb    = Q  + (long)b * S_ * D_ + (long)h * HD_ + (long)itile * 128 * D_;
  const __half* kbase = Km + (long)b * S_ * D_ + (long)h * HD_;

  if (tid < 128) rsS[tid] = 0.0f;
  float rs[4] = {0.0f, 0.0f, 0.0f, 0.0f};

  // Q tile (two 64-half blocks), one commit group.
  ld_tile(sQ,         qb,      D_, tid);
  ld_tile(sQ + TILEB, qb + KB, D_, tid);
  cp_commit();

  const int nseg = 2 * (S_ / 128 - itile);  // >= 2
  auto ld_seg = [&](int s) {
    const int jt  = itile + (s >> 1);
    const int kb2 = s & 1;
    ld_tile(sRing + (s % NST) * TILEB,
            kbase + (long)jt * 128 * D_ + kb2 * KB, D_, tid);
  };
  // prologue: NST-1 = 2 segments, one commit each
  ld_seg(0); cp_commit();
  if (nseg > 1) ld_seg(1);
  cp_commit();

  float acc[2][8][4];
  for (int s = 0; s < nseg; ++s) {
    const int jt  = itile + (s >> 1);
    const int kb2 = s & 1;
    if (kb2 == 0) {
#pragma unroll
      for (int m = 0; m < 2; ++m)
#pragma unroll
        for (int n = 0; n < 8; ++n)
#pragma unroll
          for (int c = 0; c < 4; ++c) acc[m][n][c] = 0.0f;
    }
    // pending groups at s=0: {Q, s0, s1}; wait<=1 pending => Q and s0 done.
    cp_wait<NST - 2>();
    __syncthreads();
    if (s + NST - 1 < nseg) ld_seg(s + NST - 1);
    cp_commit();
    mma_block(sQ + kb2 * TILEB, sRing + (s % NST) * TILEB,
              warpM, warpN, lane, acc);

    if (kb2 == 1) {
      if (jt > itile) {
#pragma unroll
        for (int m = 0; m < 2; ++m)
#pragma unroll
          for (int n = 0; n < 8; ++n) {
            rs[m * 2 + 0] += __expf(acc[m][n][0] * SCALE) + __expf(acc[m][n][1] * SCALE);
            rs[m * 2 + 1] += __expf(acc[m][n][2] * SCALE) + __expf(acc[m][n][3] * SCALE);
          }
      } else {
#pragma unroll
        for (int m = 0; m < 2; ++m) {
          const int li0 = warpM * 32 + m * 16 + (lane >> 2);
#pragma unroll
          for (int n = 0; n < 8; ++n) {
            const int lj = warpN * 64 + n * 8 + (lane & 3) * 2;
#pragma unroll
            for (int c = 0; c < 4; ++c) {
              const int li  = li0 + ((c >> 1) << 3);
              const int ljc = lj + (c & 1);
              if (ljc >= li) {
                const float e = __expf(acc[m][n][c] * SCALE);
                rs[m * 2 + (c >> 1)] += e;
                if (ljc == li) ediag[(long)bh * S_ + itile * 128 + li] = e;
              }
            }
          }
        }
      }
    }
  }

#pragma unroll
  for (int r = 0; r < 4; ++r) {
    rs[r] += __shfl_xor_sync(0xffffffffu, rs[r], 1);
    rs[r] += __shfl_xor_sync(0xffffffffu, rs[r], 2);
  }
  __syncthreads();
  if ((lane & 3) == 0) {
#pragma unroll
    for (int r = 0; r < 4; ++r) {
      const int li = warpM * 32 + (r >> 1) * 16 + (r & 1) * 8 + (lane >> 2);
      atomicAdd(&rsS[li], rs[r]);
    }
  }
  __syncthreads();
  if (tid < 128) {
    const int i = itile * 128 + tid;
    dinv[(long)bh * S_ + i] = 1.0f / ((float)i + rsS[tid]);
  }
}

// ---------------------------------------------------------------------------
// Single fused fp32->fp16 conversion for x + 4 weights.
// ---------------------------------------------------------------------------
__global__ void conv_all(const float4* __restrict__ x,
                         const float4* __restrict__ wq, const float4* __restrict__ wk,
                         const float4* __restrict__ wv, const float4* __restrict__ wo,
                         uint4* __restrict__ xh,
                         uint4* __restrict__ wqh, uint4* __restrict__ wkh,
                         uint4* __restrict__ wvh, uint4* __restrict__ woh) {
  const long i = (long)blockIdx.x * blockDim.x + threadIdx.x;
  const int region = (int)(i >> 19);   // NW8 = 2^19
  const long off = i & (NW8 - 1);
  const float4* src;
  uint4* dst;
  long j;
  if (region < 2)       { src = x;  dst = xh;  j = i;   }
  else if (region == 2) { src = wq; dst = wqh; j = off; }
  else if (region == 3) { src = wk; dst = wkh; j = off; }
  else if (region == 4) { src = wv; dst = wvh; j = off; }
  else                  { src = wo; dst = woh; j = off; }
  const float4 v0 = src[2 * j], v1 = src[2 * j + 1];
  uint4 o;
  o.x = h2u(__floats2half2_rn(v0.x, v0.y));
  o.y = h2u(__floats2half2_rn(v0.z, v0.w));
  o.z = h2u(__floats2half2_rn(v1.x, v1.y));
  o.w = h2u(__floats2half2_rn(v1.z, v1.w));
  dst[j] = o;
}

// ---------------------------------------------------------------------------
// V prefix-sum / combine; cc written as fp16.
// ---------------------------------------------------------------------------
__global__ void scan_pass1(const float* __restrict__ V, float* __restrict__ csum) {
  const int blk = blockIdx.x;
  const int bh = blk / NC_, c = blk % NC_;
  const int b = bh / H_, h = bh % H_;
  const int hd = threadIdx.x;
  const float* vp = V + (long)b * S_ * D_ + h * HD_ + hd;
  const int i0 = c * CH_;
  float s = 0.0f;
#pragma unroll 4
  for (int r = 0; r < CH_; ++r) s += vp[(long)(i0 + r) * D_];
  csum[(bh * NC_ + c) * HD_ + hd] = s;
}

__global__ void scan_pass2(const float* __restrict__ V, const float* __restrict__ csum,
                           const float* __restrict__ dinv, const float* __restrict__ ediag,
                           __half* __restrict__ CC) {
  const int blk = blockIdx.x;
  const int bh = blk / NC_, c = blk % NC_;
  const int b = bh / H_, h = bh % H_;
  const int hd = threadIdx.x;
  const long base = (long)b * S_ * D_ + h * HD_ + hd;
  const float* vp = V + base;
  __half* op = CC + base;
  const int i0 = c * CH_;

  float run = 0.0f;
  for (int c2 = 0; c2 < c; ++c2) run += csum[(bh * NC_ + c2) * HD_ + hd];

  for (int r = 0; r < CH_; ++r) {
    const int i = i0 + r;
    const float vv = vp[(long)i * D_];
    const float e  = ediag[bh * S_ + i];
    const float di = dinv[bh * S_ + i];
    op[(long)i * D_] = __float2half_rn((run + e * vv) * di);
    run += vv;
  }
}

// ---------------------------------------------------------------------------
extern "C" void kernel_launch(void* const* d_in, const int* in_sizes, int n_in,
                              void* d_out, int out_size) {
  const float* x   = (const float*)d_in[0];
  const float* wq  = (const float*)d_in[1];
  const float* wqb = (const float*)d_in[2];
  const float* wk  = (const float*)d_in[3];
  const float* wkb = (const float*)d_in[4];
  const float* wv  = (const float*)d_in[5];
  const float* wvb = (const float*)d_in[6];
  const float* wo  = (const float*)d_in[7];
  const float* wob = (const float*)d_in[8];
  float* out = (float*)d_out;

  __half *xh, *wqh, *wkh, *wvh, *woh, *qh, *kh, *cch;
  float *v, *dinv, *ediag, *csum;
  cudaGetSymbolAddress((void**)&xh,    g_xh);
  cudaGetSymbolAddress((void**)&wqh,   g_wqh);
  cudaGetSymbolAddress((void**)&wkh,   g_wkh);
  cudaGetSymbolAddress((void**)&wvh,   g_wvh);
  cudaGetSymbolAddress((void**)&woh,   g_woh);
  cudaGetSymbolAddress((void**)&qh,    g_qh);
  cudaGetSymbolAddress((void**)&kh,    g_kh);
  cudaGetSymbolAddress((void**)&cch,   g_cch);
  cudaGetSymbolAddress((void**)&v,     g_v);
  cudaGetSymbolAddress((void**)&dinv,  g_dinv);
  cudaGetSymbolAddress((void**)&ediag, g_ediag);
  cudaGetSymbolAddress((void**)&csum,  g_csum);

  cudaFuncSetAttribute(gemm_h,      cudaFuncAttributeMaxDynamicSharedMemorySize, DS_GEMM);
  cudaFuncSetAttribute(qk_rowsum_h, cudaFuncAttributeMaxDynamicSharedMemorySize, DS_QK);

  const long total8 = NX8 + 4 * NW8;   // 3145728
  conv_all<<<(int)(total8 / 256), 256>>>(
      (const float4*)x, (const float4*)wq, (const float4*)wk,
      (const float4*)wv, (const float4*)wo,
      (uint4*)xh, (uint4*)wqh, (uint4*)wkh, (uint4*)wvh, (uint4*)woh);

  const dim3 gg(D_ / 128, M_ / 128);   // (16, 32)
  gemm_h<<<gg, 256, DS_GEMM>>>(xh, wqh, wqb, qh, nullptr, D_);
  gemm_h<<<gg, 256, DS_GEMM>>>(xh, wkh, wkb, kh, nullptr, D_);
  gemm_h<<<gg, 256, DS_GEMM>>>(xh, wvh, wvb, nullptr, v, D_);

  const dim3 gr(S_ / 128, BH_);        // (16, 32)
  qk_rowsum_h<<<gr, 256, DS_QK>>>(qh, kh, dinv, ediag);

  scan_pass1<<<BH_ * NC_, HD_>>>(v, csum);
  scan_pass2<<<BH_ * NC_, HD_>>>(v, csum, dinv, ediag, cch);

  gemm_h<<<gg, 256, DS_GEMM>>>(cch, woh, wob, nullptr, out, D_);
}

// round 14
// speedup vs baseline: 1.8430x; 1.8430x over previous
#include <cuda_runtime.h>
#include <cuda_fp16.h>
#include <math.h>
#include <stdint.h>

// ---------------------------------------------------------------------------
// B=2, S=2048, D=2048, H=16, HD=128.
// attn[i] = ( sum_{j<i} v_j + exp(s_ii)*v_i ) / (i + sum_{j>=i} exp(s_ij))
// fp16 mma.sync m16n8k16 (fp32 accum), ldmatrix, SW128, 3-stage cp.async,
// two-barrier mainloop (proven optimal at 128 regs / 2 CTAs/SM).
// This round: z-fused QKV launch (tails/gaps paid once, not three times).
// ---------------------------------------------------------------------------

namespace {
constexpr int B_  = 2;
constexpr int S_  = 2048;
constexpr int D_  = 2048;
constexpr int H_  = 16;
constexpr int HD_ = 128;
constexpr int BH_ = B_ * H_;     // 32
constexpr int M_  = B_ * S_;     // 4096
constexpr int NC_ = 32;
constexpr int CH_ = S_ / NC_;    // 64

constexpr int KB    = 64;                  // K halfs per block (128B rows)
constexpr int TILEB = 128 * 128;           // 16KB per 128x64h tile
constexpr int NST   = 3;
constexpr unsigned DS_GEMM = NST * 2 * TILEB;         // 98304
constexpr unsigned DS_QK   = 2 * TILEB + NST * TILEB; // 81920
constexpr float SCALE = 0.02209708691207961f;  // 1/sqrt(2048)

constexpr long NX8 = (long)M_ * D_ / 8;   // 1048576 (2 regions of NW8)
constexpr long NW8 = (long)D_ * D_ / 8;   // 524288 = 2^19
}

// Scratch (static device arrays).
__device__ __half g_xh [(size_t)M_ * D_];
__device__ __half g_wqh[(size_t)D_ * D_];
__device__ __half g_wkh[(size_t)D_ * D_];
__device__ __half g_wvh[(size_t)D_ * D_];
__device__ __half g_woh[(size_t)D_ * D_];
__device__ __half g_qh [(size_t)M_ * D_];
__device__ __half g_kh [(size_t)M_ * D_];
__device__ __half g_cch[(size_t)M_ * D_];
__device__ float  g_v  [(size_t)M_ * D_];
__device__ float  g_dinv [BH_ * S_];
__device__ float  g_ediag[BH_ * S_];
__device__ float  g_csum [BH_ * NC_ * HD_];

// ---------------------------------------------------------------------------
__device__ __forceinline__ uint32_t h2u(__half2 h) {
  return *reinterpret_cast<uint32_t*>(&h);
}

__device__ __forceinline__ void cp16s(uint32_t dst, const void* src) {
  asm volatile("cp.async.cg.shared.global [%0], [%1], 16;" :: "r"(dst), "l"(src));
}
__device__ __forceinline__ void cp_commit() { asm volatile("cp.async.commit_group;"); }
template <int N> __device__ __forceinline__ void cp_wait() {
  asm volatile("cp.async.wait_group %0;" :: "n"(N));
}

__device__ __forceinline__ void mma16(float c[4], const uint32_t a[4],
                                      uint32_t b0, uint32_t b1) {
  asm volatile(
      "mma.sync.aligned.m16n8k16.row.col.f32.f16.f16.f32 "
      "{%0,%1,%2,%3},{%4,%5,%6,%7},{%8,%9},{%0,%1,%2,%3};"
      : "+f"(c[0]), "+f"(c[1]), "+f"(c[2]), "+f"(c[3])
      : "r"(a[0]), "r"(a[1]), "r"(a[2]), "r"(a[3]), "r"(b0), "r"(b1));
}

__device__ __forceinline__ void ldm4(uint32_t r[4], uint32_t addr) {
  asm volatile("ldmatrix.sync.aligned.m8n8.x4.shared.b16 {%0,%1,%2,%3}, [%4];"
               : "=r"(r[0]), "=r"(r[1]), "=r"(r[2]), "=r"(r[3]) : "r"(addr));
}

#define SWZ(x) ((x) ^ (((x) >> 3) & 0x70))

// Load a 128-row x 64-half tile (row stride ldK halfs) into swizzled smem.
__device__ __forceinline__ void ld_tile(uint32_t sbase, const __half* g,
                                        long ldK, int tid) {
#pragma unroll
  for (int i = 0; i < 4; ++i) {
    const int id  = tid + i * 256;     // 0..1023
    const int row = id >> 3;           // 0..127
    const int cb  = (id & 7) << 4;     // byte col
    const int off = row * 128 + cb;
    cp16s(sbase + SWZ(off), g + (long)row * ldK + (cb >> 1));
  }
}

// One 64-half K block: 4 k16 steps; warp tile 32x64.
__device__ __forceinline__ void mma_block(uint32_t aBase, uint32_t bBase,
                                          int warpM, int warpN, int lane,
                                          float acc[2][8][4]) {
  const int mi = lane >> 3;
  const int rA = (lane & 7) + ((mi & 1) << 3);
  const int cA = (mi >> 1) << 4;
  const int rB = (lane & 7) + ((mi >> 1) << 3);
  const int cB = (mi & 1) << 4;
#pragma unroll
  for (int ks = 0; ks < 4; ++ks) {
    const int kb = ks * 32;
    uint32_t a[2][4];
#pragma unroll
    for (int m = 0; m < 2; ++m) {
      const int off = (warpM * 32 + m * 16 + rA) * 128 + kb + cA;
      ldm4(a[m], aBase + SWZ(off));
    }
#pragma unroll
    for (int p = 0; p < 4; ++p) {
      uint32_t b[4];
      const int off = (warpN * 64 + p * 16 + rB) * 128 + kb + cB;
      ldm4(b, bBase + SWZ(off));
      mma16(acc[0][2 * p],     a[0], b[0], b[1]);
      mma16(acc[1][2 * p],     a[1], b[0], b[1]);
      mma16(acc[0][2 * p + 1], a[0], b[2], b[3]);
      mma16(acc[1][2 * p + 1], a[1], b[2], b[3]);
    }
  }
}

// R11 two-barrier multistage mainloop (proven: 128 regs, 2 CTAs/SM).
__device__ __forceinline__ void gemm_main(const __half* Ab, const __half* Bb,
                                          int K, uint32_t sb, int tid,
                                          int warpM, int warpN, int lane,
                                          float acc[2][8][4]) {
  const int NIT = K / KB;  // 32
#pragma unroll
  for (int s = 0; s < NST; ++s) {
    ld_tile(sb + s * 2 * TILEB,         Ab + s * KB, K, tid);
    ld_tile(sb + s * 2 * TILEB + TILEB, Bb + s * KB, K, tid);
    cp_commit();
  }
  for (int it = 0; it < NIT; ++it) {
    const int slot = it % NST;
    cp_wait<NST - 1>();
    __syncthreads();
    mma_block(sb + slot * 2 * TILEB, sb + slot * 2 * TILEB + TILEB,
              warpM, warpN, lane, acc);
    __syncthreads();
    if (it + NST < NIT) {
      ld_tile(sb + slot * 2 * TILEB,         Ab + (long)(it + NST) * KB, K, tid);
      ld_tile(sb + slot * 2 * TILEB + TILEB, Bb + (long)(it + NST) * KB, K, tid);
      cp_commit();
    }
  }
}

// ---------------------------------------------------------------------------
// Fused QKV GEMM: blockIdx.z selects weight/bias/output. Pointers resolved
// before the mainloop; body identical to gemm_h.
// ---------------------------------------------------------------------------
__global__ __launch_bounds__(256, 2)
void gemm_qkv(const __half* __restrict__ A,
              const __half* __restrict__ wq, const __half* __restrict__ wk,
              const __half* __restrict__ wv,
              const float* __restrict__ bq, const float* __restrict__ bk,
              const float* __restrict__ bv,
              __half* __restrict__ qh, __half* __restrict__ kh,
              float* __restrict__ vf) {
  extern __shared__ __align__(128) uint8_t dyn[];
  const uint32_t sb = (uint32_t)__cvta_generic_to_shared(dyn);
  const int tid = threadIdx.x, lane = tid & 31, warp = tid >> 5;
  const int warpM = warp & 3, warpN = warp >> 2;
  const int z = blockIdx.z;
  const __half* Bw   = (z == 0) ? wq : (z == 1) ? wk : wv;
  const float*  bias = (z == 0) ? bq : (z == 1) ? bk : bv;
  __half* Ch = (z == 0) ? qh : (z == 1) ? kh : nullptr;
  const long mBase = (long)blockIdx.y * 128;
  const long nBase = (long)blockIdx.x * 128;

  float acc[2][8][4];
#pragma unroll
  for (int m = 0; m < 2; ++m)
#pragma unroll
    for (int n = 0; n < 8; ++n)
#pragma unroll
      for (int c = 0; c < 4; ++c) acc[m][n][c] = 0.0f;

  gemm_main(A + mBase * (long)D_, Bw + nBase * (long)D_, D_, sb,
            tid, warpM, warpN, lane, acc);

#pragma unroll
  for (int m = 0; m < 2; ++m) {
    const long r0 = mBase + warpM * 32 + m * 16 + (lane >> 2);
#pragma unroll
    for (int n = 0; n < 8; ++n) {
      const long col = nBase + warpN * 64 + n * 8 + (lane & 3) * 2;
      const float b0 = bias[col], b1 = bias[col + 1];
      const float v0 = acc[m][n][0] + b0, v1 = acc[m][n][1] + b1;
      const float v2 = acc[m][n][2] + b0, v3 = acc[m][n][3] + b1;
      if (Ch) {
        *(uint32_t*)(Ch + r0 * (long)D_ + col)       = h2u(__floats2half2_rn(v0, v1));
        *(uint32_t*)(Ch + (r0 + 8) * (long)D_ + col) = h2u(__floats2half2_rn(v2, v3));
      } else {
        *(float2*)(vf + r0 * (long)D_ + col)       = make_float2(v0, v1);
        *(float2*)(vf + (r0 + 8) * (long)D_ + col) = make_float2(v2, v3);
      }
    }
  }
}

// ---------------------------------------------------------------------------
// Output projection GEMM (fp32 out).
// ---------------------------------------------------------------------------
__global__ __launch_bounds__(256, 2)
void gemm_o(const __half* __restrict__ A, const __half* __restrict__ Bw,
            const float* __restrict__ bias, float* __restrict__ Cf) {
  extern __shared__ __align__(128) uint8_t dyn[];
  const uint32_t sb = (uint32_t)__cvta_generic_to_shared(dyn);
  const int tid = threadIdx.x, lane = tid & 31, warp = tid >> 5;
  const int warpM = warp & 3, warpN = warp >> 2;
  const long mBase = (long)blockIdx.y * 128;
  const long nBase = (long)blockIdx.x * 128;

  float acc[2][8][4];
#pragma unroll
  for (int m = 0; m < 2; ++m)
#pragma unroll
    for (int n = 0; n < 8; ++n)
#pragma unroll
      for (int c = 0; c < 4; ++c) acc[m][n][c] = 0.0f;

  gemm_main(A + mBase * (long)D_, Bw + nBase * (long)D_, D_, sb,
            tid, warpM, warpN, lane, acc);

#pragma unroll
  for (int m = 0; m < 2; ++m) {
    const long r0 = mBase + warpM * 32 + m * 16 + (lane >> 2);
#pragma unroll
    for (int n = 0; n < 8; ++n) {
      const long col = nBase + warpN * 64 + n * 8 + (lane & 3) * 2;
      const float b0 = bias[col], b1 = bias[col + 1];
      *(float2*)(Cf + r0 * (long)D_ + col) =
          make_float2(acc[m][n][0] + b0, acc[m][n][1] + b1);
      *(float2*)(Cf + (r0 + 8) * (long)D_ + col) =
          make_float2(acc[m][n][2] + b0, acc[m][n][3] + b1);
    }
  }
}

// ---------------------------------------------------------------------------
// QK^T upper-triangle exp row sums. Q cached; K tiles streamed (R11 loop).
// ---------------------------------------------------------------------------
__global__ __launch_bounds__(256)
void qk_rowsum_h(const __half* __restrict__ Q, const __half* __restrict__ Km,
                 float* __restrict__ dinv, float* __restrict__ ediag) {
  extern __shared__ __align__(128) uint8_t dyn[];
  __shared__ float rsS[128];
  const uint32_t sQ    = (uint32_t)__cvta_generic_to_shared(dyn);
  const uint32_t sRing = sQ + 2 * TILEB;
  const int tid = threadIdx.x, lane = tid & 31, warp = tid >> 5;
  const int warpM = warp & 3, warpN = warp >> 2;
  const int itile = blockIdx.x, bh = blockIdx.y;
  const int b = bh >> 4, h = bh & 15;
  const __half* qb    = Q  + (long)b * S_ * D_ + (long)h * HD_ + (long)itile * 128 * D_;
  const __half* kbase = Km + (long)b * S_ * D_ + (long)h * HD_;

  if (tid < 128) rsS[tid] = 0.0f;
  float rs[4] = {0.0f, 0.0f, 0.0f, 0.0f};

  // Q tile (two 64-half blocks), loaded once.
  ld_tile(sQ,         qb,      D_, tid);
  ld_tile(sQ + TILEB, qb + KB, D_, tid);
  cp_commit();

  const int nseg = 2 * (S_ / 128 - itile);
  auto ld_seg = [&](int s) {
    const int jt  = itile + (s >> 1);
    const int kb2 = s & 1;
    ld_tile(sRing + (s % NST) * TILEB,
            kbase + (long)jt * 128 * D_ + kb2 * KB, D_, tid);
    cp_commit();
  };
  ld_seg(0);
  if (nseg > 1) ld_seg(1);
  if (nseg > 2) ld_seg(2);

  float acc[2][8][4];
  for (int s = 0; s < nseg; ++s) {
    const int jt  = itile + (s >> 1);
    const int kb2 = s & 1;
    if (kb2 == 0) {
#pragma unroll
      for (int m = 0; m < 2; ++m)
#pragma unroll
        for (int n = 0; n < 8; ++n)
#pragma unroll
          for (int c = 0; c < 4; ++c) acc[m][n][c] = 0.0f;
    }
    cp_wait<NST - 1>();
    __syncthreads();
    mma_block(sQ + kb2 * TILEB, sRing + (s % NST) * TILEB,
              warpM, warpN, lane, acc);
    __syncthreads();
    if (s + NST < nseg) ld_seg(s + NST);

    if (kb2 == 1) {
      if (jt > itile) {
#pragma unroll
        for (int m = 0; m < 2; ++m)
#pragma unroll
          for (int n = 0; n < 8; ++n) {
            rs[m * 2 + 0] += __expf(acc[m][n][0] * SCALE) + __expf(acc[m][n][1] * SCALE);
            rs[m * 2 + 1] += __expf(acc[m][n][2] * SCALE) + __expf(acc[m][n][3] * SCALE);
          }
      } else {
#pragma unroll
        for (int m = 0; m < 2; ++m) {
          const int li0 = warpM * 32 + m * 16 + (lane >> 2);
#pragma unroll
          for (int n = 0; n < 8; ++n) {
            const int lj = warpN * 64 + n * 8 + (lane & 3) * 2;
#pragma unroll
            for (int c = 0; c < 4; ++c) {
              const int li  = li0 + ((c >> 1) << 3);
              const int ljc = lj + (c & 1);
              if (ljc >= li) {
                const float e = __expf(acc[m][n][c] * SCALE);
                rs[m * 2 + (c >> 1)] += e;
                if (ljc == li) ediag[(long)bh * S_ + itile * 128 + li] = e;
              }
            }
          }
        }
      }
    }
  }

#pragma unroll
  for (int r = 0; r < 4; ++r) {
    rs[r] += __shfl_xor_sync(0xffffffffu, rs[r], 1);
    rs[r] += __shfl_xor_sync(0xffffffffu, rs[r], 2);
  }
  __syncthreads();
  if ((lane & 3) == 0) {
#pragma unroll
    for (int r = 0; r < 4; ++r) {
      const int li = warpM * 32 + (r >> 1) * 16 + (r & 1) * 8 + (lane >> 2);
      atomicAdd(&rsS[li], rs[r]);
    }
  }
  __syncthreads();
  if (tid < 128) {
    const int i = itile * 128 + tid;
    dinv[(long)bh * S_ + i] = 1.0f / ((float)i + rsS[tid]);
  }
}

// ---------------------------------------------------------------------------
// Single fused fp32->fp16 conversion for x + 4 weights.
// ---------------------------------------------------------------------------
__global__ void conv_all(const float4* __restrict__ x,
                         const float4* __restrict__ wq, const float4* __restrict__ wk,
                         const float4* __restrict__ wv, const float4* __restrict__ wo,
                         uint4* __restrict__ xh,
                         uint4* __restrict__ wqh, uint4* __restrict__ wkh,
                         uint4* __restrict__ wvh, uint4* __restrict__ woh) {
  const long i = (long)blockIdx.x * blockDim.x + threadIdx.x;
  const int region = (int)(i >> 19);   // NW8 = 2^19
  const long off = i & (NW8 - 1);
  const float4* src;
  uint4* dst;
  long j;
  if (region < 2)       { src = x;  dst = xh;  j = i;   }
  else if (region == 2) { src = wq; dst = wqh; j = off; }
  else if (region == 3) { src = wk; dst = wkh; j = off; }
  else if (region == 4) { src = wv; dst = wvh; j = off; }
  else                  { src = wo; dst = woh; j = off; }
  const float4 v0 = src[2 * j], v1 = src[2 * j + 1];
  uint4 o;
  o.x = h2u(__floats2half2_rn(v0.x, v0.y));
  o.y = h2u(__floats2half2_rn(v0.z, v0.w));
  o.z = h2u(__floats2half2_rn(v1.x, v1.y));
  o.w = h2u(__floats2half2_rn(v1.z, v1.w));
  dst[j] = o;
}

// ---------------------------------------------------------------------------
// V prefix-sum / combine; cc written as fp16.
// ---------------------------------------------------------------------------
__global__ void scan_pass1(const float* __restrict__ V, float* __restrict__ csum) {
  const int blk = blockIdx.x;
  const int bh = blk / NC_, c = blk % NC_;
  const int b = bh / H_, h = bh % H_;
  const int hd = threadIdx.x;
  const float* vp = V + (long)b * S_ * D_ + h * HD_ + hd;
  const int i0 = c * CH_;
  float s = 0.0f;
#pragma unroll 4
  for (int r = 0; r < CH_; ++r) s += vp[(long)(i0 + r) * D_];
  csum[(bh * NC_ + c) * HD_ + hd] = s;
}

__global__ void scan_pass2(const float* __restrict__ V, const float* __restrict__ csum,
                           const float* __restrict__ dinv, const float* __restrict__ ediag,
                           __half* __restrict__ CC) {
  const int blk = blockIdx.x;
  const int bh = blk / NC_, c = blk % NC_;
  const int b = bh / H_, h = bh % H_;
  const int hd = threadIdx.x;
  const long base = (long)b * S_ * D_ + h * HD_ + hd;
  const float* vp = V + base;
  __half* op = CC + base;
  const int i0 = c * CH_;

  float run = 0.0f;
  for (int c2 = 0; c2 < c; ++c2) run += csum[(bh * NC_ + c2) * HD_ + hd];

  for (int r = 0; r < CH_; ++r) {
    const int i = i0 + r;
    const float vv = vp[(long)i * D_];
    const float e  = ediag[bh * S_ + i];
    const float di = dinv[bh * S_ + i];
    op[(long)i * D_] = __float2half_rn((run + e * vv) * di);
    run += vv;
  }
}

// ---------------------------------------------------------------------------
extern "C" void kernel_launch(void* const* d_in, const int* in_sizes, int n_in,
                              void* d_out, int out_size) {
  const float* x   = (const float*)d_in[0];
  const float* wq  = (const float*)d_in[1];
  const float* wqb = (const float*)d_in[2];
  const float* wk  = (const float*)d_in[3];
  const float* wkb = (const float*)d_in[4];
  const float* wv  = (const float*)d_in[5];
  const float* wvb = (const float*)d_in[6];
  const float* wo  = (const float*)d_in[7];
  const float* wob = (const float*)d_in[8];
  float* out = (float*)d_out;

  __half *xh, *wqh, *wkh, *wvh, *woh, *qh, *kh, *cch;
  float *v, *dinv, *ediag, *csum;
  cudaGetSymbolAddress((void**)&xh,    g_xh);
  cudaGetSymbolAddress((void**)&wqh,   g_wqh);
  cudaGetSymbolAddress((void**)&wkh,   g_wkh);
  cudaGetSymbolAddress((void**)&wvh,   g_wvh);
  cudaGetSymbolAddress((void**)&woh,   g_woh);
  cudaGetSymbolAddress((void**)&qh,    g_qh);
  cudaGetSymbolAddress((void**)&kh,    g_kh);
  cudaGetSymbolAddress((void**)&cch,   g_cch);
  cudaGetSymbolAddress((void**)&v,     g_v);
  cudaGetSymbolAddress((void**)&dinv,  g_dinv);
  cudaGetSymbolAddress((void**)&ediag, g_ediag);
  cudaGetSymbolAddress((void**)&csum,  g_csum);

  cudaFuncSetAttribute(gemm_qkv,    cudaFuncAttributeMaxDynamicSharedMemorySize, DS_GEMM);
  cudaFuncSetAttribute(gemm_o,      cudaFuncAttributeMaxDynamicSharedMemorySize, DS_GEMM);
  cudaFuncSetAttribute(qk_rowsum_h, cudaFuncAttributeMaxDynamicSharedMemorySize, DS_QK);

  const long total8 = NX8 + 4 * NW8;   // 3145728
  conv_all<<<(int)(total8 / 256), 256>>>(
      (const float4*)x, (const float4*)wq, (const float4*)wk,
      (const float4*)wv, (const float4*)wo,
      (uint4*)xh, (uint4*)wqh, (uint4*)wkh, (uint4*)wvh, (uint4*)woh);

  const dim3 gq(D_ / 128, M_ / 128, 3);   // (16, 32, 3) — fused QKV
  gemm_qkv<<<gq, 256, DS_GEMM>>>(xh, wqh, wkh, wvh, wqb, wkb, wvb, qh, kh, v);

  const dim3 gr(S_ / 128, BH_);           // (16, 32)
  qk_rowsum_h<<<gr, 256, DS_QK>>>(qh, kh, dinv, ediag);

  scan_pass1<<<BH_ * NC_, HD_>>>(v, csum);
  scan_pass2<<<BH_ * NC_, HD_>>>(v, csum, dinv, ediag, cch);

  const dim3 gg(D_ / 128, M_ / 128);      // (16, 32)
  gemm_o<<<gg, 256, DS_GEMM>>>(cch, woh, wob, out);
}

// round 15
// speedup vs baseline: 1.9003x; 1.0311x over previous
#include <cuda_runtime.h>
#include <cuda_fp16.h>
#include <math.h>
#include <stdint.h>

// ---------------------------------------------------------------------------
// B=2, S=2048, D=2048, H=16, HD=128.
// attn[i] = ( sum_{j<i} v_j + exp(s_ii)*v_i ) / (i + sum_{j>=i} exp(s_ij))
// fp16 mma.sync m16n8k16 (fp32 accum), ldmatrix, SW128, 3-stage cp.async.
// This round: single-barrier mainloop UNDER __launch_bounds__(256,2)
// (R12 retry with occupancy forced) + fp16 V path.
// ---------------------------------------------------------------------------

namespace {
constexpr int B_  = 2;
constexpr int S_  = 2048;
constexpr int D_  = 2048;
constexpr int H_  = 16;
constexpr int HD_ = 128;
constexpr int BH_ = B_ * H_;     // 32
constexpr int M_  = B_ * S_;     // 4096
constexpr int NC_ = 32;
constexpr int CH_ = S_ / NC_;    // 64

constexpr int KB    = 64;                  // K halfs per block (128B rows)
constexpr int TILEB = 128 * 128;           // 16KB per 128x64h tile
constexpr int NST   = 3;
constexpr unsigned DS_GEMM = NST * 2 * TILEB;         // 98304
constexpr unsigned DS_QK   = 2 * TILEB + NST * TILEB; // 81920
constexpr float SCALE = 0.02209708691207961f;  // 1/sqrt(2048)

constexpr long NX8 = (long)M_ * D_ / 8;   // 1048576 (2 regions of NW8)
constexpr long NW8 = (long)D_ * D_ / 8;   // 524288 = 2^19
}

// Scratch (static device arrays).
__device__ __half g_xh [(size_t)M_ * D_];
__device__ __half g_wqh[(size_t)D_ * D_];
__device__ __half g_wkh[(size_t)D_ * D_];
__device__ __half g_wvh[(size_t)D_ * D_];
__device__ __half g_woh[(size_t)D_ * D_];
__device__ __half g_qh [(size_t)M_ * D_];
__device__ __half g_kh [(size_t)M_ * D_];
__device__ __half g_vh [(size_t)M_ * D_];
__device__ __half g_cch[(size_t)M_ * D_];
__device__ float  g_dinv [BH_ * S_];
__device__ float  g_ediag[BH_ * S_];
__device__ float  g_csum [BH_ * NC_ * HD_];

// ---------------------------------------------------------------------------
__device__ __forceinline__ uint32_t h2u(__half2 h) {
  return *reinterpret_cast<uint32_t*>(&h);
}

__device__ __forceinline__ void cp16s(uint32_t dst, const void* src) {
  asm volatile("cp.async.cg.shared.global [%0], [%1], 16;" :: "r"(dst), "l"(src));
}
__device__ __forceinline__ void cp_commit() { asm volatile("cp.async.commit_group;"); }
template <int N> __device__ __forceinline__ void cp_wait() {
  asm volatile("cp.async.wait_group %0;" :: "n"(N));
}

__device__ __forceinline__ void mma16(float c[4], const uint32_t a[4],
                                      uint32_t b0, uint32_t b1) {
  asm volatile(
      "mma.sync.aligned.m16n8k16.row.col.f32.f16.f16.f32 "
      "{%0,%1,%2,%3},{%4,%5,%6,%7},{%8,%9},{%0,%1,%2,%3};"
      : "+f"(c[0]), "+f"(c[1]), "+f"(c[2]), "+f"(c[3])
      : "r"(a[0]), "r"(a[1]), "r"(a[2]), "r"(a[3]), "r"(b0), "r"(b1));
}

__device__ __forceinline__ void ldm4(uint32_t r[4], uint32_t addr) {
  asm volatile("ldmatrix.sync.aligned.m8n8.x4.shared.b16 {%0,%1,%2,%3}, [%4];"
               : "=r"(r[0]), "=r"(r[1]), "=r"(r[2]), "=r"(r[3]) : "r"(addr));
}

#define SWZ(x) ((x) ^ (((x) >> 3) & 0x70))

// Load a 128-row x 64-half tile (row stride ldK halfs) into swizzled smem.
__device__ __forceinline__ void ld_tile(uint32_t sbase, const __half* g,
                                        long ldK, int tid) {
#pragma unroll
  for (int i = 0; i < 4; ++i) {
    const int id  = tid + i * 256;     // 0..1023
    const int row = id >> 3;           // 0..127
    const int cb  = (id & 7) << 4;     // byte col
    const int off = row * 128 + cb;
    cp16s(sbase + SWZ(off), g + (long)row * ldK + (cb >> 1));
  }
}

// One 64-half K block: 4 k16 steps; warp tile 32x64.
__device__ __forceinline__ void mma_block(uint32_t aBase, uint32_t bBase,
                                          int warpM, int warpN, int lane,
                                          float acc[2][8][4]) {
  const int mi = lane >> 3;
  const int rA = (lane & 7) + ((mi & 1) << 3);
  const int cA = (mi >> 1) << 4;
  const int rB = (lane & 7) + ((mi >> 1) << 3);
  const int cB = (mi & 1) << 4;
#pragma unroll
  for (int ks = 0; ks < 4; ++ks) {
    const int kb = ks * 32;
    uint32_t a[2][4];
#pragma unroll
    for (int m = 0; m < 2; ++m) {
      const int off = (warpM * 32 + m * 16 + rA) * 128 + kb + cA;
      ldm4(a[m], aBase + SWZ(off));
    }
#pragma unroll
    for (int p = 0; p < 4; ++p) {
      uint32_t b[4];
      const int off = (warpN * 64 + p * 16 + rB) * 128 + kb + cB;
      ldm4(b, bBase + SWZ(off));
      mma16(acc[0][2 * p],     a[0], b[0], b[1]);
      mma16(acc[1][2 * p],     a[1], b[0], b[1]);
      mma16(acc[0][2 * p + 1], a[0], b[2], b[3]);
      mma16(acc[1][2 * p + 1], a[1], b[2], b[3]);
    }
  }
}

// Single-barrier multistage mainloop (R12 logic; occupancy forced by caller's
// __launch_bounds__(256,2)). Race-free: the barrier at iter `it` guarantees
// compute(it-1) finished everywhere; refill targets slot (it+2)%3, last read
// at compute(it-1).
__device__ __forceinline__ void gemm_main(const __half* Ab, const __half* Bb,
                                          int K, uint32_t sb, int tid,
                                          int warpM, int warpN, int lane,
                                          float acc[2][8][4]) {
  const int NIT = K / KB;  // 32
#pragma unroll
  for (int s = 0; s < NST - 1; ++s) {
    ld_tile(sb + s * 2 * TILEB,         Ab + s * KB, K, tid);
    ld_tile(sb + s * 2 * TILEB + TILEB, Bb + s * KB, K, tid);
    cp_commit();
  }
  for (int it = 0; it < NIT; ++it) {
    cp_wait<NST - 2>();
    __syncthreads();
    const int nx = it + NST - 1;
    if (nx < NIT) {
      const int ns = nx % NST;
      ld_tile(sb + ns * 2 * TILEB,         Ab + (long)nx * KB, K, tid);
      ld_tile(sb + ns * 2 * TILEB + TILEB, Bb + (long)nx * KB, K, tid);
    }
    cp_commit();
    const int slot = it % NST;
    mma_block(sb + slot * 2 * TILEB, sb + slot * 2 * TILEB + TILEB,
              warpM, warpN, lane, acc);
  }
}

// ---------------------------------------------------------------------------
// Fused QKV GEMM: blockIdx.z selects weight/bias/output (all fp16 out now).
// ---------------------------------------------------------------------------
__global__ __launch_bounds__(256, 2)
void gemm_qkv(const __half* __restrict__ A,
              const __half* __restrict__ wq, const __half* __restrict__ wk,
              const __half* __restrict__ wv,
              const float* __restrict__ bq, const float* __restrict__ bk,
              const float* __restrict__ bv,
              __half* __restrict__ qh, __half* __restrict__ kh,
              __half* __restrict__ vh) {
  extern __shared__ __align__(128) uint8_t dyn[];
  const uint32_t sb = (uint32_t)__cvta_generic_to_shared(dyn);
  const int tid = threadIdx.x, lane = tid & 31, warp = tid >> 5;
  const int warpM = warp & 3, warpN = warp >> 2;
  const int z = blockIdx.z;
  const __half* Bw   = (z == 0) ? wq : (z == 1) ? wk : wv;
  const float*  bias = (z == 0) ? bq : (z == 1) ? bk : bv;
  __half* Ch = (z == 0) ? qh : (z == 1) ? kh : vh;
  const long mBase = (long)blockIdx.y * 128;
  const long nBase = (long)blockIdx.x * 128;

  float acc[2][8][4];
#pragma unroll
  for (int m = 0; m < 2; ++m)
#pragma unroll
    for (int n = 0; n < 8; ++n)
#pragma unroll
      for (int c = 0; c < 4; ++c) acc[m][n][c] = 0.0f;

  gemm_main(A + mBase * (long)D_, Bw + nBase * (long)D_, D_, sb,
            tid, warpM, warpN, lane, acc);

#pragma unroll
  for (int m = 0; m < 2; ++m) {
    const long r0 = mBase + warpM * 32 + m * 16 + (lane >> 2);
#pragma unroll
    for (int n = 0; n < 8; ++n) {
      const long col = nBase + warpN * 64 + n * 8 + (lane & 3) * 2;
      const float b0 = bias[col], b1 = bias[col + 1];
      *(uint32_t*)(Ch + r0 * (long)D_ + col) =
          h2u(__floats2half2_rn(acc[m][n][0] + b0, acc[m][n][1] + b1));
      *(uint32_t*)(Ch + (r0 + 8) * (long)D_ + col) =
          h2u(__floats2half2_rn(acc[m][n][2] + b0, acc[m][n][3] + b1));
    }
  }
}

// ---------------------------------------------------------------------------
// Output projection GEMM (fp32 out).
// ---------------------------------------------------------------------------
__global__ __launch_bounds__(256, 2)
void gemm_o(const __half* __restrict__ A, const __half* __restrict__ Bw,
            const float* __restrict__ bias, float* __restrict__ Cf) {
  extern __shared__ __align__(128) uint8_t dyn[];
  const uint32_t sb = (uint32_t)__cvta_generic_to_shared(dyn);
  const int tid = threadIdx.x, lane = tid & 31, warp = tid >> 5;
  const int warpM = warp & 3, warpN = warp >> 2;
  const long mBase = (long)blockIdx.y * 128;
  const long nBase = (long)blockIdx.x * 128;

  float acc[2][8][4];
#pragma unroll
  for (int m = 0; m < 2; ++m)
#pragma unroll
    for (int n = 0; n < 8; ++n)
#pragma unroll
      for (int c = 0; c < 4; ++c) acc[m][n][c] = 0.0f;

  gemm_main(A + mBase * (long)D_, Bw + nBase * (long)D_, D_, sb,
            tid, warpM, warpN, lane, acc);

#pragma unroll
  for (int m = 0; m < 2; ++m) {
    const long r0 = mBase + warpM * 32 + m * 16 + (lane >> 2);
#pragma unroll
    for (int n = 0; n < 8; ++n) {
      const long col = nBase + warpN * 64 + n * 8 + (lane & 3) * 2;
      const float b0 = bias[col], b1 = bias[col + 1];
      *(float2*)(Cf + r0 * (long)D_ + col) =
          make_float2(acc[m][n][0] + b0, acc[m][n][1] + b1);
      *(float2*)(Cf + (r0 + 8) * (long)D_ + col) =
          make_float2(acc[m][n][2] + b0, acc[m][n][3] + b1);
    }
  }
}

// ---------------------------------------------------------------------------
// QK^T upper-triangle exp row sums. Q cached; K tiles streamed; one barrier.
// ---------------------------------------------------------------------------
__global__ __launch_bounds__(256, 2)
void qk_rowsum_h(const __half* __restrict__ Q, const __half* __restrict__ Km,
                 float* __restrict__ dinv, float* __restrict__ ediag) {
  extern __shared__ __align__(128) uint8_t dyn[];
  __shared__ float rsS[128];
  const uint32_t sQ    = (uint32_t)__cvta_generic_to_shared(dyn);
  const uint32_t sRing = sQ + 2 * TILEB;
  const int tid = threadIdx.x, lane = tid & 31, warp = tid >> 5;
  const int warpM = warp & 3, warpN = warp >> 2;
  const int itile = blockIdx.x, bh = blockIdx.y;
  const int b = bh >> 4, h = bh & 15;
  const __half* qb    = Q  + (long)b * S_ * D_ + (long)h * HD_ + (long)itile * 128 * D_;
  const __half* kbase = Km + (long)b * S_ * D_ + (long)h * HD_;

  if (tid < 128) rsS[tid] = 0.0f;
  float rs[4] = {0.0f, 0.0f, 0.0f, 0.0f};

  // Q tile (two 64-half blocks), one commit group.
  ld_tile(sQ,         qb,      D_, tid);
  ld_tile(sQ + TILEB, qb + KB, D_, tid);
  cp_commit();

  const int nseg = 2 * (S_ / 128 - itile);  // >= 2
  auto ld_seg = [&](int s) {
    const int jt  = itile + (s >> 1);
    const int kb2 = s & 1;
    ld_tile(sRing + (s % NST) * TILEB,
            kbase + (long)jt * 128 * D_ + kb2 * KB, D_, tid);
  };
  // prologue: 2 segments, one commit each. Pending: {Q, s0, s1}.
  ld_seg(0); cp_commit();
  if (nseg > 1) ld_seg(1);
  cp_commit();

  float acc[2][8][4];
  for (int s = 0; s < nseg; ++s) {
    const int jt  = itile + (s >> 1);
    const int kb2 = s & 1;
    if (kb2 == 0) {
#pragma unroll
      for (int m = 0; m < 2; ++m)
#pragma unroll
        for (int n = 0; n < 8; ++n)
#pragma unroll
          for (int c = 0; c < 4; ++c) acc[m][n][c] = 0.0f;
    }
    // s=0: wait<=1 pending => Q and s0 complete.
    cp_wait<NST - 2>();
    __syncthreads();
    if (s + NST - 1 < nseg) ld_seg(s + NST - 1);
    cp_commit();
    mma_block(sQ + kb2 * TILEB, sRing + (s % NST) * TILEB,
              warpM, warpN, lane, acc);

    if (kb2 == 1) {
      if (jt > itile) {
#pragma unroll
        for (int m = 0; m < 2; ++m)
#pragma unroll
          for (int n = 0; n < 8; ++n) {
            rs[m * 2 + 0] += __expf(acc[m][n][0] * SCALE) + __expf(acc[m][n][1] * SCALE);
            rs[m * 2 + 1] += __expf(acc[m][n][2] * SCALE) + __expf(acc[m][n][3] * SCALE);
          }
      } else {
#pragma unroll
        for (int m = 0; m < 2; ++m) {
          const int li0 = warpM * 32 + m * 16 + (lane >> 2);
#pragma unroll
          for (int n = 0; n < 8; ++n) {
            const int lj = warpN * 64 + n * 8 + (lane & 3) * 2;
#pragma unroll
            for (int c = 0; c < 4; ++c) {
              const int li  = li0 + ((c >> 1) << 3);
              const int ljc = lj + (c & 1);
              if (ljc >= li) {
                const float e = __expf(acc[m][n][c] * SCALE);
                rs[m * 2 + (c >> 1)] += e;
                if (ljc == li) ediag[(long)bh * S_ + itile * 128 + li] = e;
              }
            }
          }
        }
      }
    }
  }

#pragma unroll
  for (int r = 0; r < 4; ++r) {
    rs[r] += __shfl_xor_sync(0xffffffffu, rs[r], 1);
    rs[r] += __shfl_xor_sync(0xffffffffu, rs[r], 2);
  }
  __syncthreads();
  if ((lane & 3) == 0) {
#pragma unroll
    for (int r = 0; r < 4; ++r) {
      const int li = warpM * 32 + (r >> 1) * 16 + (r & 1) * 8 + (lane >> 2);
      atomicAdd(&rsS[li], rs[r]);
    }
  }
  __syncthreads();
  if (tid < 128) {
    const int i = itile * 128 + tid;
    dinv[(long)bh * S_ + i] = 1.0f / ((float)i + rsS[tid]);
  }
}

// ---------------------------------------------------------------------------
// Single fused fp32->fp16 conversion for x + 4 weights.
// ---------------------------------------------------------------------------
__global__ void conv_all(const float4* __restrict__ x,
                         const float4* __restrict__ wq, const float4* __restrict__ wk,
                         const float4* __restrict__ wv, const float4* __restrict__ wo,
                         uint4* __restrict__ xh,
                         uint4* __restrict__ wqh, uint4* __restrict__ wkh,
                         uint4* __restrict__ wvh, uint4* __restrict__ woh) {
  const long i = (long)blockIdx.x * blockDim.x + threadIdx.x;
  const int region = (int)(i >> 19);   // NW8 = 2^19
  const long off = i & (NW8 - 1);
  const float4* src;
  uint4* dst;
  long j;
  if (region < 2)       { src = x;  dst = xh;  j = i;   }
  else if (region == 2) { src = wq; dst = wqh; j = off; }
  else if (region == 3) { src = wk; dst = wkh; j = off; }
  else if (region == 4) { src = wv; dst = wvh; j = off; }
  else                  { src = wo; dst = woh; j = off; }
  const float4 v0 = src[2 * j], v1 = src[2 * j + 1];
  uint4 o;
  o.x = h2u(__floats2half2_rn(v0.x, v0.y));
  o.y = h2u(__floats2half2_rn(v0.z, v0.w));
  o.z = h2u(__floats2half2_rn(v1.x, v1.y));
  o.w = h2u(__floats2half2_rn(v1.z, v1.w));
  dst[j] = o;
}

// ---------------------------------------------------------------------------
// V prefix-sum / combine; V fp16 in, fp32 accumulate, cc fp16 out.
// ---------------------------------------------------------------------------
__global__ void scan_pass1(const __half* __restrict__ V, float* __restrict__ csum) {
  const int blk = blockIdx.x;
  const int bh = blk / NC_, c = blk % NC_;
  const int b = bh / H_, h = bh % H_;
  const int hd = threadIdx.x;
  const __half* vp = V + (long)b * S_ * D_ + h * HD_ + hd;
  const int i0 = c * CH_;
  float s = 0.0f;
#pragma unroll 4
  for (int r = 0; r < CH_; ++r) s += __half2float(vp[(long)(i0 + r) * D_]);
  csum[(bh * NC_ + c) * HD_ + hd] = s;
}

__global__ void scan_pass2(const __half* __restrict__ V, const float* __restrict__ csum,
                           const float* __restrict__ dinv, const float* __restrict__ ediag,
                           __half* __restrict__ CC) {
  const int blk = blockIdx.x;
  const int bh = blk / NC_, c = blk % NC_;
  const int b = bh / H_, h = bh % H_;
  const int hd = threadIdx.x;
  const long base = (long)b * S_ * D_ + h * HD_ + hd;
  const __half* vp = V + base;
  __half* op = CC + base;
  const int i0 = c * CH_;

  float run = 0.0f;
  for (int c2 = 0; c2 < c; ++c2) run += csum[(bh * NC_ + c2) * HD_ + hd];

  for (int r = 0; r < CH_; ++r) {
    const int i = i0 + r;
    const float vv = __half2float(vp[(long)i * D_]);
    const float e  = ediag[bh * S_ + i];
    const float di = dinv[bh * S_ + i];
    op[(long)i * D_] = __float2half_rn((run + e * vv) * di);
    run += vv;
  }
}

// ---------------------------------------------------------------------------
extern "C" void kernel_launch(void* const* d_in, const int* in_sizes, int n_in,
                              void* d_out, int out_size) {
  const float* x   = (const float*)d_in[0];
  const float* wq  = (const float*)d_in[1];
  const float* wqb = (const float*)d_in[2];
  const float* wk  = (const float*)d_in[3];
  const float* wkb = (const float*)d_in[4];
  const float* wv  = (const float*)d_in[5];
  const float* wvb = (const float*)d_in[6];
  const float* wo  = (const float*)d_in[7];
  const float* wob = (const float*)d_in[8];
  float* out = (float*)d_out;

  __half *xh, *wqh, *wkh, *wvh, *woh, *qh, *kh, *vh, *cch;
  float *dinv, *ediag, *csum;
  cudaGetSymbolAddress((void**)&xh,    g_xh);
  cudaGetSymbolAddress((void**)&wqh,   g_wqh);
  cudaGetSymbolAddress((void**)&wkh,   g_wkh);
  cudaGetSymbolAddress((void**)&wvh,   g_wvh);
  cudaGetSymbolAddress((void**)&woh,   g_woh);
  cudaGetSymbolAddress((void**)&qh,    g_qh);
  cudaGetSymbolAddress((void**)&kh,    g_kh);
  cudaGetSymbolAddress((void**)&vh,    g_vh);
  cudaGetSymbolAddress((void**)&cch,   g_cch);
  cudaGetSymbolAddress((void**)&dinv,  g_dinv);
  cudaGetSymbolAddress((void**)&ediag, g_ediag);
  cudaGetSymbolAddress((void**)&csum,  g_csum);

  cudaFuncSetAttribute(gemm_qkv,    cudaFuncAttributeMaxDynamicSharedMemorySize, DS_GEMM);
  cudaFuncSetAttribute(gemm_o,      cudaFuncAttributeMaxDynamicSharedMemorySize, DS_GEMM);
  cudaFuncSetAttribute(qk_rowsum_h, cudaFuncAttributeMaxDynamicSharedMemorySize, DS_QK);

  const long total8 = NX8 + 4 * NW8;   // 3145728
  conv_all<<<(int)(total8 / 256), 256>>>(
      (const float4*)x, (const float4*)wq, (const float4*)wk,
      (const float4*)wv, (const float4*)wo,
      (uint4*)xh, (uint4*)wqh, (uint4*)wkh, (uint4*)wvh, (uint4*)woh);

  const dim3 gq(D_ / 128, M_ / 128, 3);   // (16, 32, 3) — fused QKV
  gemm_qkv<<<gq, 256, DS_GEMM>>>(xh, wqh, wkh, wvh, wqb, wkb, wvb, qh, kh, vh);

  const dim3 gr(S_ / 128, BH_);           // (16, 32)
  qk_rowsum_h<<<gr, 256, DS_QK>>>(qh, kh, dinv, ediag);

  scan_pass1<<<BH_ * NC_, HD_>>>(vh, csum);
  scan_pass2<<<BH_ * NC_, HD_>>>(vh, csum, dinv, ediag, cch);

  const dim3 gg(D_ / 128, M_ / 128);      // (16, 32)
  gemm_o<<<gg, 256, DS_GEMM>>>(cch, woh, wob, out);
}